// round 1
// baseline (speedup 1.0000x reference)
#include <cuda_runtime.h>
#include <cuda_bf16.h>
#include <stdint.h>

// GCN mean aggregation:
//   out[i, :] = mean over {nodes[i]} ∪ neigh_idx[i, 0..K-1] of features[idx, :]
// Shapes: features [V=100000, D=128] f32, nodes [B=50000] int{32|64},
//         neigh_idx [B, K=32] int{32|64}, out [B, 128] f32.
//
// Strategy: one warp per node. Each lane owns one float4 column slice
// (32 lanes * 16B = 512B = one full feature row, perfectly coalesced).
// 33 gathers fully unrolled for MLP. Table (51MB) fits in L2, so replays
// are L2-throughput bound.

static constexpr int D4 = 32;    // 128 floats = 32 float4 per row
static constexpr int KN = 32;    // neighbors per node
static constexpr float INV_CNT = 1.0f / 33.0f;

// Runtime index-dtype detection (JAX may demote int64 -> int32).
__device__ int g_idx_is64;

__global__ void detect_idx_dtype(const int* __restrict__ p) {
    // If the buffer holds little-endian int64 values in [0, 2^31), every odd
    // 32-bit word is zero. For real int32 indices in [0, 100000) the odds of
    // 64 consecutive odd words all being zero are ~0.
    int all0 = 1;
#pragma unroll
    for (int i = 0; i < 64; i++) all0 &= (p[2 * i + 1] == 0);
    g_idx_is64 = all0;
}

__global__ __launch_bounds__(256, 8) void gcn_agg_kernel(
    const float4* __restrict__ feat,
    const void*   __restrict__ nodes,
    const void*   __restrict__ neigh,
    float4*       __restrict__ out,
    int B)
{
    const int gwarp = (blockIdx.x * blockDim.x + threadIdx.x) >> 5;
    const int lane  = threadIdx.x & 31;
    if (gwarp >= B) return;

    const int is64 = g_idx_is64;

    // Fetch the 33 row indices (uniform across the warp -> L1 broadcast).
    int idxs[KN + 1];
    if (is64) {
        const long long* n64 = (const long long*)nodes;
        const long long* g64 = (const long long*)neigh + (long long)gwarp * KN;
        idxs[0] = (int)__ldg(n64 + gwarp);
#pragma unroll
        for (int j = 0; j < KN; j++) idxs[j + 1] = (int)__ldg(g64 + j);
    } else {
        const int* n32 = (const int*)nodes;
        const int* g32 = (const int*)neigh + (long long)gwarp * KN;
        idxs[0] = __ldg(n32 + gwarp);
#pragma unroll
        for (int j = 0; j < KN; j++) idxs[j + 1] = __ldg(g32 + j);
    }

    // Gather + accumulate. Fully unrolled so ptxas batches the LDG.128s
    // (high MLP per warp; latency hidden across 50k warps).
    float4 acc = make_float4(0.f, 0.f, 0.f, 0.f);
#pragma unroll
    for (int j = 0; j < KN + 1; j++) {
        const float4 v = __ldg(feat + (long long)idxs[j] * D4 + lane);
        acc.x += v.x; acc.y += v.y; acc.z += v.z; acc.w += v.w;
    }

    acc.x *= INV_CNT; acc.y *= INV_CNT; acc.z *= INV_CNT; acc.w *= INV_CNT;
    out[(long long)gwarp * D4 + lane] = acc;
}

extern "C" void kernel_launch(void* const* d_in, const int* in_sizes, int n_in,
                              void* d_out, int out_size) {
    const float4* feat  = (const float4*)d_in[0];
    const void*   nodes = d_in[1];
    const void*   neigh = d_in[2];
    float4*       out   = (float4*)d_out;

    const int B = in_sizes[1];  // 50000

    detect_idx_dtype<<<1, 1>>>((const int*)nodes);

    const int threads = 256;                 // 8 warps/block
    const int warps_needed = B;
    const int blocks = (warps_needed * 32 + threads - 1) / threads;
    gcn_agg_kernel<<<blocks, threads>>>(feat, nodes, neigh, out, B);
}

// round 3
// speedup vs baseline: 1.6996x; 1.6996x over previous
#include <cuda_runtime.h>
#include <cuda_bf16.h>
#include <stdint.h>

// GCN mean aggregation:
//   out[i, :] = mean over {nodes[i]} ∪ neigh_idx[i, 0..K-1] of features[idx, :]
// features [V=100000, D=128] f32, nodes [B] int{32|64}, neigh [B,32] int{32|64}.
//
// One warp per node; lane = one float4 slice (32x16B = full 512B row,
// coalesced). L2 is the binding resource (~6300 B/cyc LTS cap), so:
//  - feature loads use an L2::evict_last cache policy (table reused ~16.5x,
//    keep resident) via createpolicy + L2::cache_hint (the only legal form
//    for 16B vectors on sm_103 ptxas)
//  - index loads + output stores use streaming (.cs) hints (read/write-once)
//  - indices fetched with ONE coalesced 256B load + shfl broadcast.

static constexpr int D4 = 32;    // 128 floats = 32 float4/row
static constexpr int KN = 32;
static constexpr float INV_CNT = 1.0f / 33.0f;

__device__ int g_idx_is64;

__global__ void detect_idx_dtype(const int* __restrict__ p) {
    // little-endian int64 values < 2^31 have all odd 32-bit words zero
    int all0 = 1;
#pragma unroll
    for (int i = 0; i < 64; i++) all0 &= (p[2 * i + 1] == 0);
    g_idx_is64 = all0;
}

__device__ __forceinline__ uint64_t make_keep_policy() {
    uint64_t pol;
    asm("createpolicy.fractional.L2::evict_last.b64 %0, 1.0;" : "=l"(pol));
    return pol;
}

__device__ __forceinline__ float4 ldg_keep(const float4* p, uint64_t pol) {
    float4 v;
    asm volatile("ld.global.nc.L2::cache_hint.v4.f32 {%0,%1,%2,%3}, [%4], %5;"
                 : "=f"(v.x), "=f"(v.y), "=f"(v.z), "=f"(v.w)
                 : "l"(p), "l"(pol));
    return v;
}

__device__ __forceinline__ void stg_stream(float4* p, float4 v) {
    asm volatile("st.global.cs.v4.f32 [%0], {%1,%2,%3,%4};"
                 :: "l"(p), "f"(v.x), "f"(v.y), "f"(v.z), "f"(v.w) : "memory");
}

__device__ __forceinline__ long long ldg_cs64(const long long* p) {
    long long v;
    asm volatile("ld.global.cs.s64 %0, [%1];" : "=l"(v) : "l"(p));
    return v;
}

__device__ __forceinline__ int ldg_cs32(const int* p) {
    int v;
    asm volatile("ld.global.cs.s32 %0, [%1];" : "=r"(v) : "l"(p));
    return v;
}

__global__ __launch_bounds__(256) void gcn_agg_kernel(
    const float4* __restrict__ feat,
    const void*   __restrict__ nodes,
    const void*   __restrict__ neigh,
    float4*       __restrict__ out,
    int B)
{
    const int gwarp = (blockIdx.x * blockDim.x + threadIdx.x) >> 5;
    const int lane  = threadIdx.x & 31;
    if (gwarp >= B) return;

    // Coalesced index fetch: lane j owns neigh[gwarp][j]; self idx broadcast.
    int my_idx, self_idx;
    if (g_idx_is64) {
        my_idx   = (int)ldg_cs64((const long long*)neigh + (long long)gwarp * KN + lane);
        self_idx = (int)ldg_cs64((const long long*)nodes + gwarp);
    } else {
        my_idx   = ldg_cs32((const int*)neigh + (long long)gwarp * KN + lane);
        self_idx = ldg_cs32((const int*)nodes + gwarp);
    }

    const uint64_t pol = make_keep_policy();

    float4 acc;
    {   // self row
        acc = ldg_keep(feat + (long long)self_idx * D4 + lane, pol);
    }
#pragma unroll
    for (int j = 0; j < KN; j++) {
        const int idx = __shfl_sync(0xffffffffu, my_idx, j);
        const float4 v = ldg_keep(feat + (long long)idx * D4 + lane, pol);
        acc.x += v.x; acc.y += v.y; acc.z += v.z; acc.w += v.w;
    }

    acc.x *= INV_CNT; acc.y *= INV_CNT; acc.z *= INV_CNT; acc.w *= INV_CNT;
    stg_stream(out + (long long)gwarp * D4 + lane, acc);
}

extern "C" void kernel_launch(void* const* d_in, const int* in_sizes, int n_in,
                              void* d_out, int out_size) {
    const float4* feat  = (const float4*)d_in[0];
    const void*   nodes = d_in[1];
    const void*   neigh = d_in[2];
    float4*       out   = (float4*)d_out;

    const int B = in_sizes[1];  // 50000

    detect_idx_dtype<<<1, 1>>>((const int*)nodes);

    const int threads = 256;
    const int blocks  = (B * 32 + threads - 1) / threads;
    gcn_agg_kernel<<<blocks, threads>>>(feat, nodes, neigh, out, B);
}